// round 4
// baseline (speedup 1.0000x reference)
#include <cuda_runtime.h>

namespace {
constexpr int H = 128, Wd = 128;
constexpr int PLANE = H * Wd;          // 16384
constexpr int NBLOCKS = 32 * 64;       // 2048 planes
constexpr int RPW = 16;                // rows per warp (8 warps)
constexpr int TBL = 9 * 25;            // 225 WL entries (LDS table)
}

struct RowS {
    float x[6];   // [0]=left edge, [1..4]=own 4 cols, [5]=right edge
    int   b[6];   // bins
};

__device__ __forceinline__ float4 ldrow(const float* __restrict__ xp, int r,
                                        int lane) {
    float4 v = make_float4(0.f, 0.f, 0.f, 0.f);
    if ((unsigned)r < (unsigned)H)
        v = __ldg(reinterpret_cast<const float4*>(xp + r * Wd + lane * 4));
    return v;
}

__device__ __forceinline__ void build(float4 v, int lane, RowS& R) {
    R.x[1] = v.x; R.x[2] = v.y; R.x[3] = v.z; R.x[4] = v.w;
#pragma unroll
    for (int i = 1; i <= 4; ++i)
        R.b[i] = (int)fminf(R.x[i] * 5.0f, 4.0f);   // x>=0; floor==trunc
    R.x[0] = __shfl_up_sync(0xffffffffu, v.w, 1);
    R.b[0] = __shfl_up_sync(0xffffffffu, R.b[4], 1);
    R.x[5] = __shfl_down_sync(0xffffffffu, v.x, 1);
    R.b[5] = __shfl_down_sync(0xffffffffu, R.b[1], 1);
    if (lane == 0)  R.x[0] = 0.f;   // x=0 kills the term; b irrelevant
    if (lane == 31) R.x[5] = 0.f;
}

__global__ __launch_bounds__(256, 4)
void col_kernel(const float* __restrict__ x,
                const float* __restrict__ Wp,
                const float* __restrict__ Lp,
                float* __restrict__ out) {
    // LDS table for the 6 lower terms (dh=1,2): bank-replicated, lane l only
    // touches bank l. addr = laneBase + bp*128 + bq*640 + o*3200 (o = 0..5
    // covering dh=1,2).
    __shared__ float sWL[6 * 25 * 32];

    for (int t = threadIdx.x; t < 6 * 25 * 32; t += 256) {
        int idx = t >> 5;               // o6*25 + bq*5 + bp   (o6 = o-3)
        int o6 = idx / 25;
        int i  = idx - o6 * 25;
        sWL[t] = Wp[o6 + 3] * Lp[i];
    }

    // Shuffle tables for the 3 top-row terms (dh=0): one entry per lane.
    // Lane l (l<25) holds W[0][k] * L[l], l = bq*5 + bp.
    const int lane = threadIdx.x & 31;
    float lval = (lane < 25) ? __ldg(Lp + lane) : 0.f;
    const float WL0 = __ldg(Wp + 0) * lval;
    const float WL1 = __ldg(Wp + 1) * lval;
    const float WL2 = __ldg(Wp + 2) * lval;
    __syncthreads();

    const int plane = blockIdx.x;
    const float* xp = x + (size_t)plane * PLANE;
    float* op = out + (size_t)plane * PLANE;

    const int warp = threadIdx.x >> 5;
    const int r0 = warp * RPW;
    const char* laneBase = reinterpret_cast<const char*>(sWL) + lane * 4;

    RowS Rr[3];
    float4 wv[2];
    build(ldrow(xp, r0 - 1, lane), lane, Rr[0]);
    build(ldrow(xp, r0,     lane), lane, Rr[1]);
    wv[0] = ldrow(xp, r0 + 1, lane);

#pragma unroll
    for (int k = 0; k < RPW; ++k) {
        const int r = r0 + k;
        wv[(k + 1) & 1] = ldrow(xp, r + 2, lane);   // prefetch (OOB -> zeros)
        build(wv[k & 1], lane, Rr[(k + 2) % 3]);    // loaded last iteration

        const RowS& A  = Rr[k % 3];
        const RowS& Bc = Rr[(k + 1) % 3];
        const RowS& Cn = Rr[(k + 2) % 3];

        float res[4];
#pragma unroll
        for (int i = 0; i < 4; ++i) {
            const int bp = Bc.b[i + 1];

            // dh=0 row via shuffle-table gather (zero l1tex traffic)
            float sA;
            {
                int l0 = A.b[i + 0] * 5 + bp;
                int l1 = A.b[i + 1] * 5 + bp;
                int l2 = A.b[i + 2] * 5 + bp;
                sA  = __shfl_sync(0xffffffffu, WL0, l0) * A.x[i + 0];
                sA += __shfl_sync(0xffffffffu, WL1, l1) * A.x[i + 1];
                sA += __shfl_sync(0xffffffffu, WL2, l2) * A.x[i + 2];
            }

            // dh=1,2 rows via replicated LDS table
            const char* pb = laneBase + bp * 128;
            float sL = 0.f;
#define COL_TERM(R, o6, dw)                                                    \
            sL += *reinterpret_cast<const float*>(                             \
                      pb + (R).b[i + (dw)] * 640 + (o6) * 3200)                \
                  * (R).x[i + (dw)];
            COL_TERM(Bc, 0, 0) COL_TERM(Bc, 1, 1) COL_TERM(Bc, 2, 2)
            COL_TERM(Cn, 3, 0) COL_TERM(Cn, 4, 1) COL_TERM(Cn, 5, 2)
#undef COL_TERM
            res[i] = sA + sL;
        }

        *reinterpret_cast<float4*>(op + r * Wd + lane * 4) =
            make_float4(res[0], res[1], res[2], res[3]);
    }
}

extern "C" void kernel_launch(void* const* d_in, const int* in_sizes, int n_in,
                              void* d_out, int out_size) {
    const float* x = nullptr;
    const float* W = nullptr;
    const float* L = nullptr;
    for (int i = 0; i < n_in; ++i) {
        if (in_sizes[i] == 9)       W = (const float*)d_in[i];
        else if (in_sizes[i] == 25) L = (const float*)d_in[i];
        else                        x = (const float*)d_in[i];
    }
    col_kernel<<<NBLOCKS, 256>>>(x, W, L, (float*)d_out);
}